// round 12
// baseline (speedup 1.0000x reference)
#include <cuda_runtime.h>
#include <cuda_fp16.h>
#include <cstdint>
#include <cstddef>

// ---------------- problem constants ----------------
constexpr int LQ    = 13294;
constexpr int MROWS = 2 * LQ;          // 26588
constexpr int MPAD  = 208 * 128;       // 26624

__constant__ int c_WH[4] = {100, 50, 25, 13};
__constant__ int c_ST[4] = {0, 10000, 12500, 13125};

// ---------------- scratch (device globals) ----------------
__device__ __half g_value[MPAD * 256];            // fp16 value tensor
__device__ float  g_qc   [MPAD * 384];            // [off(256) | logits(128)] per row
__device__ float  g_samp [MPAD * 256];
__device__ float  g_bqc  [384];                   // boff ++ battn
// transposed fp16 weights: Wv [0,256), Wqc [256,640), Wout [640,896)
__device__ __half g_wt[896 * 256];

// ---------------- PTX helpers (baseline sm_80+ ISA, legal on compute_103) ----
__device__ __forceinline__ uint32_t smem_u32(const void* p) {
    uint32_t a;
    asm("{ .reg .u64 t; cvta.to.shared.u64 t, %1; cvt.u32.u64 %0, t; }" : "=r"(a) : "l"(p));
    return a;
}
__device__ __forceinline__ void ldsm_x4(uint32_t addr, uint32_t* r) {
    asm volatile("ldmatrix.sync.aligned.m8n8.x4.shared.b16 {%0,%1,%2,%3}, [%4];"
                 : "=r"(r[0]), "=r"(r[1]), "=r"(r[2]), "=r"(r[3]) : "r"(addr));
}
__device__ __forceinline__ void mma_f16(float* c, const uint32_t* a, const uint32_t* b) {
    asm volatile("mma.sync.aligned.m16n8k16.row.col.f32.f16.f16.f32 "
                 "{%0,%1,%2,%3}, {%4,%5,%6,%7}, {%8,%9}, {%0,%1,%2,%3};"
                 : "+f"(c[0]), "+f"(c[1]), "+f"(c[2]), "+f"(c[3])
                 : "r"(a[0]), "r"(a[1]), "r"(a[2]), "r"(a[3]), "r"(b[0]), "r"(b[1]));
}
#define CP_ASYNC16(dst, src) \
    asm volatile("cp.async.cg.shared.global [%0], [%1], 16;" :: "r"(dst), "l"(src) : "memory")
#define CP_COMMIT() asm volatile("cp.async.commit_group;" ::: "memory")
#define CP_WAIT1()  asm volatile("cp.async.wait_group 1;" ::: "memory")

// ---------------- weight conversion (one launch) ----------------
__global__ __launch_bounds__(256) void conv_wt_all(
    const float* __restrict__ Wv,   const float* __restrict__ Woff,
    const float* __restrict__ Wattn,const float* __restrict__ Wout,
    const float* __restrict__ boff, const float* __restrict__ battn,
    __half* __restrict__ wt, float* __restrict__ bqc)
{
    int idx = blockIdx.x * 256 + threadIdx.x;     // 896*256 total
    int ng = idx >> 8, k = idx & 255;
    float a;
    if (ng < 256)       a = Wv  [k * 256 + ng];
    else if (ng < 640) {
        int n = ng - 256;
        a = (n < 256) ? Woff[k * 256 + n] : Wattn[k * 128 + (n - 256)];
    } else              a = Wout[k * 256 + (ng - 640)];
    wt[idx] = __float2half_rn(a);
    if (idx < 384) bqc[idx] = (idx < 256) ? boff[idx] : battn[idx - 256];
}

// ---------------- fused-convert HMMA GEMM core (fp16, BM=128 BN=64) --------
// C[M,N] = A16[M,256] @ Wt^T + bias.
// 256 threads, 8 warps, warp tile 32x32. 3 CTAs/SM (regs ~80, smem 35.8KB).
// A: fp32 LDG -> fp16 smem (2 buffers). B: cp.async 3-stage ring.
constexpr int ASTG  = 10240;                       // A buffer: 128 rows x 80B
constexpr int BSTG  = 5120;                        // B stage:   64 rows x 80B
constexpr int BBASE = 2 * ASTG;                    // 20480
constexpr int GSMEM = BBASE + 3 * BSTG;            // 35840

template <bool HalfOut>
__device__ __forceinline__ void gemm_core(
    const float* __restrict__ A,
    const __half* __restrict__ B,
    const float* __restrict__ bias, void* __restrict__ Cv,
    int M, int ldc, int m0, int n0, char* smem)
{
    const uint32_t sm0 = smem_u32(smem);
    const int tid = threadIdx.x, wid = tid >> 5, lane = tid & 31;
    const int wm = (wid & 3) * 32, wn = (wid >> 2) * 32;

    const int arow = tid >> 1, ak0 = (tid & 1) * 16;
    const bool avalid = (m0 + arow) < M;
    const float* aptr = A + (size_t)(m0 + arow) * 256 + ak0;

    const int brow = tid >> 2, bchk = tid & 3;     // 64 rows x 4 chunks of 16B

    const uint32_t aRow = (lane & 15), aColB = (uint32_t)(lane >> 4) * 16;
    const uint32_t bRow = ((uint32_t)(lane >> 4) << 3) + (lane & 7);
    const uint32_t bColB = (uint32_t)((lane >> 3) & 1) * 16;

    float acc[2][4][4] = {};
    float fA[16];

    auto ldgA = [&](int ch) {
        if (avalid) {
            const float* p = aptr + ch * 32;
            #pragma unroll
            for (int j = 0; j < 4; ++j)
                *(float4*)&fA[j * 4] = *(const float4*)(p + j * 4);
        } else {
            #pragma unroll
            for (int j = 0; j < 16; ++j) fA[j] = 0.f;
        }
    };
    auto cvtStoreA = [&](uint32_t off) {
        __half h[16];
        #pragma unroll
        for (int j = 0; j < 16; ++j) h[j] = __float2half_rn(fA[j]);
        const uint32_t o = arow * 80 + ak0 * 2;
        *(uint4*)(smem + off + o)      = ((uint4*)h)[0];
        *(uint4*)(smem + off + o + 16) = ((uint4*)h)[1];
    };
    auto ldB = [&](int ch) {
        const uint32_t sb = sm0 + BBASE + (ch % 3) * BSTG;
        const int k0 = ch * 32;
        CP_ASYNC16(sb + brow * 80 + bchk * 16,
                   B + (size_t)(n0 + brow) * 256 + k0 + bchk * 8);
        CP_COMMIT();
    };

    ldB(0); ldB(1);
    ldgA(0);
    cvtStoreA(0);

    for (int ch = 0; ch < 8; ++ch) {
        CP_WAIT1();
        __syncthreads();
        if (ch < 6) ldB(ch + 2); else CP_COMMIT();
        if (ch < 7) ldgA(ch + 1);

        const uint32_t sa = sm0 + (ch & 1) * ASTG;
        const uint32_t sb = sm0 + BBASE + (ch % 3) * BSTG;
        #pragma unroll
        for (int ks = 0; ks < 2; ++ks) {
            const uint32_t kB = ks * 32;
            uint32_t af[2][4], bf[2][4];
            #pragma unroll
            for (int mt = 0; mt < 2; ++mt)
                ldsm_x4(sa + (wm + mt * 16 + aRow) * 80 + kB + aColB, af[mt]);
            #pragma unroll
            for (int p = 0; p < 2; ++p)
                ldsm_x4(sb + (wn + p * 16 + bRow) * 80 + kB + bColB, bf[p]);
            #pragma unroll
            for (int mt = 0; mt < 2; ++mt)
                #pragma unroll
                for (int nt = 0; nt < 4; ++nt)
                    mma_f16(acc[mt][nt], af[mt], &bf[nt >> 1][(nt & 1) * 2]);
        }

        if (ch < 7) cvtStoreA(((ch + 1) & 1) * ASTG);
    }

    const int g = lane >> 2, t2 = (lane & 3) * 2;
    #pragma unroll
    for (int mt = 0; mt < 2; ++mt) {
        const int r0 = m0 + wm + mt * 16 + g;
        #pragma unroll
        for (int nt = 0; nt < 4; ++nt) {
            const int c = n0 + wn + nt * 8 + t2;
            const float2 bsv = *(const float2*)(bias + c);
            if (HalfOut) {
                __half* C = (__half*)Cv;
                if (r0 < M)
                    *(__half2*)(C + (size_t)r0 * ldc + c) =
                        __floats2half2_rn(acc[mt][nt][0] + bsv.x, acc[mt][nt][1] + bsv.y);
                if (r0 + 8 < M)
                    *(__half2*)(C + (size_t)(r0 + 8) * ldc + c) =
                        __floats2half2_rn(acc[mt][nt][2] + bsv.x, acc[mt][nt][3] + bsv.y);
            } else {
                float* C = (float*)Cv;
                if (r0 < M) {
                    float2 o = { acc[mt][nt][0] + bsv.x, acc[mt][nt][1] + bsv.y };
                    *(float2*)(C + (size_t)r0 * ldc + c) = o;
                }
                if (r0 + 8 < M) {
                    float2 o = { acc[mt][nt][2] + bsv.x, acc[mt][nt][3] + bsv.y };
                    *(float2*)(C + (size_t)(r0 + 8) * ldc + c) = o;
                }
            }
        }
    }
}

// merged value+qc GEMM: grid.y in [0,10): y<4 -> value fp16 (N=256), y>=4 -> qc fp32 (N=384)
__global__ __launch_bounds__(256, 3) void gemm_dual(
    const float* __restrict__ A0, const __half* __restrict__ B0,
    const float* __restrict__ bias0, __half* __restrict__ C0,
    const float* __restrict__ A1, const __half* __restrict__ B1,
    const float* __restrict__ bias1, float* __restrict__ C1)
{
    extern __shared__ __align__(16) char smem[];
    const int m0 = blockIdx.x * 128;
    if (blockIdx.y < 4)
        gemm_core<true >(A0, B0, bias0, C0, MROWS, 256, m0, blockIdx.y * 64, smem);
    else
        gemm_core<false>(A1, B1, bias1, C1, MROWS, 384, m0, (blockIdx.y - 4) * 64, smem);
}

__global__ __launch_bounds__(256, 3) void gemm_single(
    const float* __restrict__ A, const __half* __restrict__ B,
    const float* __restrict__ bias, float* __restrict__ C, int M, int ldc)
{
    extern __shared__ __align__(16) char smem[];
    gemm_core<false>(A, B, bias, C, M, ldc, blockIdx.x * 128, blockIdx.y * 64, smem);
}

// ---------------- deformable sampling: fp16 value, precomputed corner table ----
__global__ __launch_bounds__(256) void sample_kernel(
    const float* __restrict__ refpts,   // [N*Lq, 4, 2]
    const __half* __restrict__ value,   // [N*S, 256] fp16
    const float* __restrict__ qc,       // [N*Lq, 384]: off(256) | logits(128)
    float* __restrict__ out)            // [N*Lq, 256]
{
    const int q0  = blockIdx.x * 4;
    const int tid = threadIdx.x;

    __shared__ float sh_w[4][8][17];
    __shared__ float sh_x[4][8][17];
    __shared__ float sh_y[4][8][17];
    __shared__ __align__(16) float2 sh_p[4][8][64];

    // softmax weights: 32 runs of 16 logits, 16-lane segments
    #pragma unroll
    for (int i = 0; i < 2; ++i) {
        int run = i * 16 + (tid >> 4);
        int q = run >> 3, h = run & 7, l16 = tid & 15;
        float v = qc[(size_t)(q0 + q) * 384 + 256 + h * 16 + l16];
        float mx = v;
        #pragma unroll
        for (int o = 8; o > 0; o >>= 1) mx = fmaxf(mx, __shfl_xor_sync(0xffffffffu, mx, o));
        float e = __expf(v - mx);
        float s = e;
        #pragma unroll
        for (int o = 8; o > 0; o >>= 1) s += __shfl_xor_sync(0xffffffffu, s, o);
        sh_w[q][h][l16] = e / s;
    }

    // pixel coords: x = ref*W + off - 0.5
    #pragma unroll
    for (int q = 0; q < 4; ++q) {
        int h = tid >> 5, l32 = tid & 31;
        int lvl = l32 >> 3, cc = l32 & 1, s = l32 >> 1;
        float off = qc[(size_t)(q0 + q) * 384 + tid];
        float ref = refpts[((size_t)(q0 + q) * 4 + lvl) * 2 + cc];
        float pix = fmaf(ref, (float)c_WH[lvl], off) - 0.5f;
        if (cc == 0) sh_x[q][h][s] = pix; else sh_y[q][h][s] = pix;
    }
    __syncthreads();

    // 2048 corners, 8 per thread: (q,h,s,c) -> (gw, byteoff)  [512B per position]
    #pragma unroll
    for (int i = 0; i < 8; ++i) {
        const int e = i * 256 + tid;
        const int q = e >> 9, h = (e >> 6) & 7, s = (e >> 2) & 15, c = e & 3;
        const int lvl = s >> 2;
        const int Wl = c_WH[lvl], st = c_ST[lvl];
        const float x = sh_x[q][h][s], y = sh_y[q][h][s], aw = sh_w[q][h][s];
        const float xf = floorf(x), yf = floorf(y);
        const float wx = x - xf, wy = y - yf;
        const int xi = (int)xf + (c & 1);
        const int yi = (int)yf + (c >> 1);
        const float gw = aw * ((c >> 1) ? wy : 1.f - wy) * ((c & 1) ? wx : 1.f - wx);
        const bool valid = (xi >= 0) & (xi < Wl) & (yi >= 0) & (yi < Wl);
        float2 pr;
        pr.x = valid ? gw : 0.f;
        pr.y = __int_as_float(valid ? (st + yi * Wl + xi) * 512 : 0);
        sh_p[q][h][s * 4 + c] = pr;
    }
    __syncthreads();

    // gather: warp = (query, head-half); lane: 4 heads x 8 slots of 4 fp16 channels
    const int w = tid >> 5, lane = tid & 31;
    const int q = w >> 1, half = w & 1;
    const int head = half * 4 + (lane >> 3);
    const int ci = lane & 7;
    const int qg = q0 + q;
    const int n  = (qg >= LQ) ? 1 : 0;

    const char* vb = (const char*)value + ((size_t)n * LQ * 256 + head * 32 + ci * 4) * 2;
    const float4* pp = (const float4*)&sh_p[q][head][0];
    float4 acc = make_float4(0.f, 0.f, 0.f, 0.f);

    #pragma unroll 8
    for (int i = 0; i < 32; ++i) {
        const float4 pw = pp[i];
        const uint2 r0 = __ldg((const uint2*)(vb + (uint32_t)__float_as_int(pw.y)));
        const uint2 r1 = __ldg((const uint2*)(vb + (uint32_t)__float_as_int(pw.w)));
        const float2 a0 = __half22float2(*(const __half2*)&r0.x);
        const float2 a1 = __half22float2(*(const __half2*)&r0.y);
        const float2 b0 = __half22float2(*(const __half2*)&r1.x);
        const float2 b1 = __half22float2(*(const __half2*)&r1.y);
        acc.x = fmaf(pw.x, a0.x, acc.x);
        acc.y = fmaf(pw.x, a0.y, acc.y);
        acc.z = fmaf(pw.x, a1.x, acc.z);
        acc.w = fmaf(pw.x, a1.y, acc.w);
        acc.x = fmaf(pw.z, b0.x, acc.x);
        acc.y = fmaf(pw.z, b0.y, acc.y);
        acc.z = fmaf(pw.z, b1.x, acc.z);
        acc.w = fmaf(pw.z, b1.y, acc.w);
    }
    ((float4*)out)[(size_t)qg * 64 + head * 8 + ci] = acc;
}

// ---------------- launch (single stream) ----------------
extern "C" void kernel_launch(void* const* d_in, const int* in_sizes, int n_in,
                              void* d_out, int out_size)
{
    const float* query  = (const float*)d_in[0];
    const float* refpts = (const float*)d_in[1];
    const float* flat   = (const float*)d_in[2];
    const float* Wv     = (const float*)d_in[5];
    const float* bv     = (const float*)d_in[6];
    const float* Woff   = (const float*)d_in[7];
    const float* boff   = (const float*)d_in[8];
    const float* Wattn  = (const float*)d_in[9];
    const float* battn  = (const float*)d_in[10];
    const float* Wout   = (const float*)d_in[11];
    const float* bout   = (const float*)d_in[12];
    float* out = (float*)d_out;

    __half* gv;
    float *gqc, *gs, *gbqc;
    __half *wt;
    cudaGetSymbolAddress((void**)&gv,   g_value);
    cudaGetSymbolAddress((void**)&gqc,  g_qc);
    cudaGetSymbolAddress((void**)&gs,   g_samp);
    cudaGetSymbolAddress((void**)&gbqc, g_bqc);
    cudaGetSymbolAddress((void**)&wt,   g_wt);

    static bool attr_done = false;
    if (!attr_done) {
        cudaFuncSetAttribute(gemm_dual,   cudaFuncAttributeMaxDynamicSharedMemorySize, GSMEM);
        cudaFuncSetAttribute(gemm_single, cudaFuncAttributeMaxDynamicSharedMemorySize, GSMEM);
        attr_done = true;
    }

    __half *wv = wt + 0, *wq = wt + 256 * 256, *wu = wt + 640 * 256;

    conv_wt_all<<<896, 256>>>(Wv, Woff, Wattn, Wout, boff, battn, wt, gbqc);

    const int mblk = MPAD / 128;           // 208
    gemm_dual<<<dim3(mblk, 10), 256, GSMEM>>>(flat, wv, bv, gv,
                                              query, wq, gbqc, gqc);
    sample_kernel<<<MROWS / 4, 256>>>(refpts, gv, gqc, gs);
    gemm_single<<<dim3(mblk, 4), 256, GSMEM>>>(gs, wu, bout, out, MROWS, 256);
}

// round 13
// speedup vs baseline: 1.1440x; 1.1440x over previous
#include <cuda_runtime.h>
#include <cuda_fp16.h>
#include <cstdint>
#include <cstddef>

// ---------------- problem constants ----------------
constexpr int LQ    = 13294;
constexpr int MROWS = 2 * LQ;          // 26588
constexpr int MPAD  = 208 * 128;       // 26624

__constant__ int c_WH[4] = {100, 50, 25, 13};
__constant__ int c_ST[4] = {0, 10000, 12500, 13125};

// ---------------- scratch (device globals) ----------------
__device__ __half g_value[MPAD * 256];            // fp16 value tensor
__device__ float  g_qc   [MPAD * 384];            // [off(256) | logits(128)] per row
__device__ float  g_samp [MPAD * 256];
__device__ float  g_bqc  [384];                   // boff ++ battn
// transposed fp16 weights: Wv [0,256), Wqc [256,640), Wout [640,896)
__device__ __half g_wt[896 * 256];

// ---------------- PTX helpers (baseline sm_80+ ISA, legal on compute_103) ----
__device__ __forceinline__ uint32_t smem_u32(const void* p) {
    uint32_t a;
    asm("{ .reg .u64 t; cvta.to.shared.u64 t, %1; cvt.u32.u64 %0, t; }" : "=r"(a) : "l"(p));
    return a;
}
__device__ __forceinline__ void ldsm_x4(uint32_t addr, uint32_t* r) {
    asm volatile("ldmatrix.sync.aligned.m8n8.x4.shared.b16 {%0,%1,%2,%3}, [%4];"
                 : "=r"(r[0]), "=r"(r[1]), "=r"(r[2]), "=r"(r[3]) : "r"(addr));
}
__device__ __forceinline__ void mma_f16(float* c, const uint32_t* a, const uint32_t* b) {
    asm volatile("mma.sync.aligned.m16n8k16.row.col.f32.f16.f16.f32 "
                 "{%0,%1,%2,%3}, {%4,%5,%6,%7}, {%8,%9}, {%0,%1,%2,%3};"
                 : "+f"(c[0]), "+f"(c[1]), "+f"(c[2]), "+f"(c[3])
                 : "r"(a[0]), "r"(a[1]), "r"(a[2]), "r"(a[3]), "r"(b[0]), "r"(b[1]));
}
#define CP_ASYNC16(dst, src) \
    asm volatile("cp.async.cg.shared.global [%0], [%1], 16;" :: "r"(dst), "l"(src) : "memory")
#define CP_COMMIT() asm volatile("cp.async.commit_group;" ::: "memory")
#define CP_WAIT1()  asm volatile("cp.async.wait_group 1;" ::: "memory")

// ---------------- weight conversion (one launch) ----------------
__global__ __launch_bounds__(256) void conv_wt_all(
    const float* __restrict__ Wv,   const float* __restrict__ Woff,
    const float* __restrict__ Wattn,const float* __restrict__ Wout,
    const float* __restrict__ boff, const float* __restrict__ battn,
    __half* __restrict__ wt, float* __restrict__ bqc)
{
    int idx = blockIdx.x * 256 + threadIdx.x;     // 896*256 total
    int ng = idx >> 8, k = idx & 255;
    float a;
    if (ng < 256)       a = Wv  [k * 256 + ng];
    else if (ng < 640) {
        int n = ng - 256;
        a = (n < 256) ? Woff[k * 256 + n] : Wattn[k * 128 + (n - 256)];
    } else              a = Wout[k * 256 + (ng - 640)];
    wt[idx] = __float2half_rn(a);
    if (idx < 384) bqc[idx] = (idx < 256) ? boff[idx] : battn[idx - 256];
}

// ---------------- fused-convert HMMA GEMM core (fp16, BM=64 BN=128) --------
// C[M,N] = A16[M,256] @ Wt^T + bias.
// 256 threads, 8 warps, warp tile 32x32 (wm 2 x wn 4). 3 CTAs/SM.
// A: fp32 LDG -> fp16 smem (2 buffers). B: cp.async 3-stage ring.
constexpr int ASTG  = 5120;                        // A buffer:  64 rows x 80B
constexpr int BSTG  = 10240;                       // B stage:  128 rows x 80B
constexpr int BBASE = 2 * ASTG;                    // 10240
constexpr int GSMEM = BBASE + 3 * BSTG;            // 40960 -> 3 CTAs/SM

template <bool HalfOut>
__device__ __forceinline__ void gemm_core(
    const float* __restrict__ A,
    const __half* __restrict__ B,
    const float* __restrict__ bias, void* __restrict__ Cv,
    int M, int ldc, int m0, int n0, char* smem)
{
    const uint32_t sm0 = smem_u32(smem);
    const int tid = threadIdx.x, wid = tid >> 5, lane = tid & 31;
    const int wm = (wid & 1) * 32, wn = (wid >> 1) * 32;

    // A: 64 rows x 32 fp32 per chunk; thread -> (row = tid>>2, 8 floats at (tid&3)*8)
    const int arow = tid >> 2, ak0 = (tid & 3) * 8;
    const bool avalid = (m0 + arow) < M;
    const float* aptr = A + (size_t)(m0 + arow) * 256 + ak0;

    // B: 128 rows x 4 chunks of 16B; thread -> row = tid>>1, chunks (tid&1)*2 +i
    const int brow = tid >> 1, bc2 = (tid & 1) * 2;

    const uint32_t aRow = (lane & 15), aColB = (uint32_t)(lane >> 4) * 16;
    const uint32_t bRow = ((uint32_t)(lane >> 4) << 3) + (lane & 7);
    const uint32_t bColB = (uint32_t)((lane >> 3) & 1) * 16;

    float acc[2][4][4] = {};
    float fA[8];

    auto ldgA = [&](int ch) {
        if (avalid) {
            const float* p = aptr + ch * 32;
            *(float4*)&fA[0] = *(const float4*)(p);
            *(float4*)&fA[4] = *(const float4*)(p + 4);
        } else {
            #pragma unroll
            for (int j = 0; j < 8; ++j) fA[j] = 0.f;
        }
    };
    auto cvtStoreA = [&](uint32_t off) {
        __half h[8];
        #pragma unroll
        for (int j = 0; j < 8; ++j) h[j] = __float2half_rn(fA[j]);
        *(uint4*)(smem + off + arow * 80 + ak0 * 2) = *(uint4*)h;
    };
    auto ldB = [&](int ch) {
        const uint32_t sb = sm0 + BBASE + (ch % 3) * BSTG;
        const int k0 = ch * 32;
        #pragma unroll
        for (int i = 0; i < 2; ++i) {
            const int c = bc2 + i;
            CP_ASYNC16(sb + brow * 80 + c * 16,
                       B + (size_t)(n0 + brow) * 256 + k0 + c * 8);
        }
        CP_COMMIT();
    };

    ldB(0); ldB(1);
    ldgA(0);
    cvtStoreA(0);

    for (int ch = 0; ch < 8; ++ch) {
        CP_WAIT1();
        __syncthreads();
        if (ch < 6) ldB(ch + 2); else CP_COMMIT();
        if (ch < 7) ldgA(ch + 1);

        const uint32_t sa = sm0 + (ch & 1) * ASTG;
        const uint32_t sb = sm0 + BBASE + (ch % 3) * BSTG;
        #pragma unroll
        for (int ks = 0; ks < 2; ++ks) {
            const uint32_t kB = ks * 32;
            uint32_t af[2][4], bf[2][4];
            #pragma unroll
            for (int mt = 0; mt < 2; ++mt)
                ldsm_x4(sa + (wm + mt * 16 + aRow) * 80 + kB + aColB, af[mt]);
            #pragma unroll
            for (int p = 0; p < 2; ++p)
                ldsm_x4(sb + (wn + p * 16 + bRow) * 80 + kB + bColB, bf[p]);
            #pragma unroll
            for (int mt = 0; mt < 2; ++mt)
                #pragma unroll
                for (int nt = 0; nt < 4; ++nt)
                    mma_f16(acc[mt][nt], af[mt], &bf[nt >> 1][(nt & 1) * 2]);
        }

        if (ch < 7) cvtStoreA(((ch + 1) & 1) * ASTG);
    }

    const int g = lane >> 2, t2 = (lane & 3) * 2;
    #pragma unroll
    for (int mt = 0; mt < 2; ++mt) {
        const int r0 = m0 + wm + mt * 16 + g;
        #pragma unroll
        for (int nt = 0; nt < 4; ++nt) {
            const int c = n0 + wn + nt * 8 + t2;
            const float2 bsv = *(const float2*)(bias + c);
            if (HalfOut) {
                __half* C = (__half*)Cv;
                if (r0 < M)
                    *(__half2*)(C + (size_t)r0 * ldc + c) =
                        __floats2half2_rn(acc[mt][nt][0] + bsv.x, acc[mt][nt][1] + bsv.y);
                if (r0 + 8 < M)
                    *(__half2*)(C + (size_t)(r0 + 8) * ldc + c) =
                        __floats2half2_rn(acc[mt][nt][2] + bsv.x, acc[mt][nt][3] + bsv.y);
            } else {
                float* C = (float*)Cv;
                if (r0 < M) {
                    float2 o = { acc[mt][nt][0] + bsv.x, acc[mt][nt][1] + bsv.y };
                    *(float2*)(C + (size_t)r0 * ldc + c) = o;
                }
                if (r0 + 8 < M) {
                    float2 o = { acc[mt][nt][2] + bsv.x, acc[mt][nt][3] + bsv.y };
                    *(float2*)(C + (size_t)(r0 + 8) * ldc + c) = o;
                }
            }
        }
    }
}

// merged value+qc GEMM: grid.y in [0,5): y<2 -> value fp16 (N=256), y>=2 -> qc fp32 (N=384)
__global__ __launch_bounds__(256, 3) void gemm_dual(
    const float* __restrict__ A0, const __half* __restrict__ B0,
    const float* __restrict__ bias0, __half* __restrict__ C0,
    const float* __restrict__ A1, const __half* __restrict__ B1,
    const float* __restrict__ bias1, float* __restrict__ C1)
{
    extern __shared__ __align__(16) char smem[];
    const int m0 = blockIdx.x * 64;
    if (blockIdx.y < 2)
        gemm_core<true >(A0, B0, bias0, C0, MROWS, 256, m0, blockIdx.y * 128, smem);
    else
        gemm_core<false>(A1, B1, bias1, C1, MROWS, 384, m0, (blockIdx.y - 2) * 128, smem);
}

__global__ __launch_bounds__(256, 3) void gemm_single(
    const float* __restrict__ A, const __half* __restrict__ B,
    const float* __restrict__ bias, float* __restrict__ C, int M, int ldc)
{
    extern __shared__ __align__(16) char smem[];
    gemm_core<false>(A, B, bias, C, M, ldc, blockIdx.x * 64, blockIdx.y * 128, smem);
}

// ---------------- deformable sampling: fp16 value, precomputed corner table ----
__global__ __launch_bounds__(256) void sample_kernel(
    const float* __restrict__ refpts,   // [N*Lq, 4, 2]
    const __half* __restrict__ value,   // [N*S, 256] fp16
    const float* __restrict__ qc,       // [N*Lq, 384]: off(256) | logits(128)
    float* __restrict__ out)            // [N*Lq, 256]
{
    const int q0  = blockIdx.x * 4;
    const int tid = threadIdx.x;

    __shared__ float sh_w[4][8][17];
    __shared__ float sh_x[4][8][17];
    __shared__ float sh_y[4][8][17];
    __shared__ __align__(16) float2 sh_p[4][8][64];

    // softmax weights: 32 runs of 16 logits, 16-lane segments
    #pragma unroll
    for (int i = 0; i < 2; ++i) {
        int run = i * 16 + (tid >> 4);
        int q = run >> 3, h = run & 7, l16 = tid & 15;
        float v = qc[(size_t)(q0 + q) * 384 + 256 + h * 16 + l16];
        float mx = v;
        #pragma unroll
        for (int o = 8; o > 0; o >>= 1) mx = fmaxf(mx, __shfl_xor_sync(0xffffffffu, mx, o));
        float e = __expf(v - mx);
        float s = e;
        #pragma unroll
        for (int o = 8; o > 0; o >>= 1) s += __shfl_xor_sync(0xffffffffu, s, o);
        sh_w[q][h][l16] = e / s;
    }

    // pixel coords: x = ref*W + off - 0.5
    #pragma unroll
    for (int q = 0; q < 4; ++q) {
        int h = tid >> 5, l32 = tid & 31;
        int lvl = l32 >> 3, cc = l32 & 1, s = l32 >> 1;
        float off = qc[(size_t)(q0 + q) * 384 + tid];
        float ref = refpts[((size_t)(q0 + q) * 4 + lvl) * 2 + cc];
        float pix = fmaf(ref, (float)c_WH[lvl], off) - 0.5f;
        if (cc == 0) sh_x[q][h][s] = pix; else sh_y[q][h][s] = pix;
    }
    __syncthreads();

    // 2048 corners, 8 per thread: (q,h,s,c) -> (gw, byteoff)  [512B per position]
    #pragma unroll
    for (int i = 0; i < 8; ++i) {
        const int e = i * 256 + tid;
        const int q = e >> 9, h = (e >> 6) & 7, s = (e >> 2) & 15, c = e & 3;
        const int lvl = s >> 2;
        const int Wl = c_WH[lvl], st = c_ST[lvl];
        const float x = sh_x[q][h][s], y = sh_y[q][h][s], aw = sh_w[q][h][s];
        const float xf = floorf(x), yf = floorf(y);
        const float wx = x - xf, wy = y - yf;
        const int xi = (int)xf + (c & 1);
        const int yi = (int)yf + (c >> 1);
        const float gw = aw * ((c >> 1) ? wy : 1.f - wy) * ((c & 1) ? wx : 1.f - wx);
        const bool valid = (xi >= 0) & (xi < Wl) & (yi >= 0) & (yi < Wl);
        float2 pr;
        pr.x = valid ? gw : 0.f;
        pr.y = __int_as_float(valid ? (st + yi * Wl + xi) * 512 : 0);
        sh_p[q][h][s * 4 + c] = pr;
    }
    __syncthreads();

    // gather: warp = (query, head-half); lane: 4 heads x 8 slots of 4 fp16 channels
    const int w = tid >> 5, lane = tid & 31;
    const int q = w >> 1, half = w & 1;
    const int head = half * 4 + (lane >> 3);
    const int ci = lane & 7;
    const int qg = q0 + q;
    const int n  = (qg >= LQ) ? 1 : 0;

    const char* vb = (const char*)value + ((size_t)n * LQ * 256 + head * 32 + ci * 4) * 2;
    const float4* pp = (const float4*)&sh_p[q][head][0];
    float4 acc = make_float4(0.f, 0.f, 0.f, 0.f);

    #pragma unroll 8
    for (int i = 0; i < 32; ++i) {
        const float4 pw = pp[i];
        const uint2 r0 = __ldg((const uint2*)(vb + (uint32_t)__float_as_int(pw.y)));
        const uint2 r1 = __ldg((const uint2*)(vb + (uint32_t)__float_as_int(pw.w)));
        const float2 a0 = __half22float2(*(const __half2*)&r0.x);
        const float2 a1 = __half22float2(*(const __half2*)&r0.y);
        const float2 b0 = __half22float2(*(const __half2*)&r1.x);
        const float2 b1 = __half22float2(*(const __half2*)&r1.y);
        acc.x = fmaf(pw.x, a0.x, acc.x);
        acc.y = fmaf(pw.x, a0.y, acc.y);
        acc.z = fmaf(pw.x, a1.x, acc.z);
        acc.w = fmaf(pw.x, a1.y, acc.w);
        acc.x = fmaf(pw.z, b0.x, acc.x);
        acc.y = fmaf(pw.z, b0.y, acc.y);
        acc.z = fmaf(pw.z, b1.x, acc.z);
        acc.w = fmaf(pw.z, b1.y, acc.w);
    }
    ((float4*)out)[(size_t)qg * 64 + head * 8 + ci] = acc;
}

// ---------------- launch (single stream) ----------------
extern "C" void kernel_launch(void* const* d_in, const int* in_sizes, int n_in,
                              void* d_out, int out_size)
{
    const float* query  = (const float*)d_in[0];
    const float* refpts = (const float*)d_in[1];
    const float* flat   = (const float*)d_in[2];
    const float* Wv     = (const float*)d_in[5];
    const float* bv     = (const float*)d_in[6];
    const float* Woff   = (const float*)d_in[7];
    const float* boff   = (const float*)d_in[8];
    const float* Wattn  = (const float*)d_in[9];
    const float* battn  = (const float*)d_in[10];
    const float* Wout   = (const float*)d_in[11];
    const float* bout   = (const float*)d_in[12];
    float* out = (float*)d_out;

    __half* gv;
    float *gqc, *gs, *gbqc;
    __half *wt;
    cudaGetSymbolAddress((void**)&gv,   g_value);
    cudaGetSymbolAddress((void**)&gqc,  g_qc);
    cudaGetSymbolAddress((void**)&gs,   g_samp);
    cudaGetSymbolAddress((void**)&gbqc, g_bqc);
    cudaGetSymbolAddress((void**)&wt,   g_wt);

    static bool attr_done = false;
    if (!attr_done) {
        cudaFuncSetAttribute(gemm_dual,   cudaFuncAttributeMaxDynamicSharedMemorySize, GSMEM);
        cudaFuncSetAttribute(gemm_single, cudaFuncAttributeMaxDynamicSharedMemorySize, GSMEM);
        attr_done = true;
    }

    __half *wv = wt + 0, *wq = wt + 256 * 256, *wu = wt + 640 * 256;

    conv_wt_all<<<896, 256>>>(Wv, Woff, Wattn, Wout, boff, battn, wt, gbqc);

    const int mblk = MPAD / 64;            // 416
    gemm_dual<<<dim3(mblk, 5), 256, GSMEM>>>(flat, wv, bv, gv,
                                             query, wq, gbqc, gqc);
    sample_kernel<<<MROWS / 4, 256>>>(refpts, gv, gqc, gs);
    gemm_single<<<dim3(mblk, 2), 256, GSMEM>>>(gs, wu, bout, out, MROWS, 256);
}

// round 14
// speedup vs baseline: 1.2263x; 1.0719x over previous
#include <cuda_runtime.h>
#include <cuda_fp16.h>
#include <cstdint>
#include <cstddef>

// ---------------- problem constants ----------------
constexpr int LQ    = 13294;
constexpr int MROWS = 2 * LQ;          // 26588
constexpr int MPAD  = 208 * 128;       // 26624

__constant__ int c_WH[4] = {100, 50, 25, 13};
__constant__ int c_ST[4] = {0, 10000, 12500, 13125};

// ---------------- scratch (device globals) ----------------
__device__ __half g_value[MPAD * 256];            // fp16 value tensor
__device__ float  g_qc   [MPAD * 384];            // [off(256) | logits(128)] per row
__device__ __half g_samp [MPAD * 256];            // fp16 sampled output (pad rows stay 0)
__device__ float  g_bqc  [384];                   // boff ++ battn
// transposed fp16 weights: Wv [0,256), Wqc [256,640), Wout [640,896)
__device__ __half g_wt[896 * 256];

// ---------------- PTX helpers (baseline sm_80+ ISA, legal on compute_103) ----
__device__ __forceinline__ uint32_t smem_u32(const void* p) {
    uint32_t a;
    asm("{ .reg .u64 t; cvta.to.shared.u64 t, %1; cvt.u32.u64 %0, t; }" : "=r"(a) : "l"(p));
    return a;
}
__device__ __forceinline__ void ldsm_x4(uint32_t addr, uint32_t* r) {
    asm volatile("ldmatrix.sync.aligned.m8n8.x4.shared.b16 {%0,%1,%2,%3}, [%4];"
                 : "=r"(r[0]), "=r"(r[1]), "=r"(r[2]), "=r"(r[3]) : "r"(addr));
}
__device__ __forceinline__ void mma_f16(float* c, const uint32_t* a, const uint32_t* b) {
    asm volatile("mma.sync.aligned.m16n8k16.row.col.f32.f16.f16.f32 "
                 "{%0,%1,%2,%3}, {%4,%5,%6,%7}, {%8,%9}, {%0,%1,%2,%3};"
                 : "+f"(c[0]), "+f"(c[1]), "+f"(c[2]), "+f"(c[3])
                 : "r"(a[0]), "r"(a[1]), "r"(a[2]), "r"(a[3]), "r"(b[0]), "r"(b[1]));
}
#define CP_ASYNC16(dst, src) \
    asm volatile("cp.async.cg.shared.global [%0], [%1], 16;" :: "r"(dst), "l"(src) : "memory")
#define CP_COMMIT() asm volatile("cp.async.commit_group;" ::: "memory")
#define CP_WAIT1()  asm volatile("cp.async.wait_group 1;" ::: "memory")

// ---------------- weight conversion (one launch) ----------------
__global__ __launch_bounds__(256) void conv_wt_all(
    const float* __restrict__ Wv,   const float* __restrict__ Woff,
    const float* __restrict__ Wattn,const float* __restrict__ Wout,
    const float* __restrict__ boff, const float* __restrict__ battn,
    __half* __restrict__ wt, float* __restrict__ bqc)
{
    int idx = blockIdx.x * 256 + threadIdx.x;     // 896*256 total
    int ng = idx >> 8, k = idx & 255;
    float a;
    if (ng < 256)       a = Wv  [k * 256 + ng];
    else if (ng < 640) {
        int n = ng - 256;
        a = (n < 256) ? Woff[k * 256 + n] : Wattn[k * 128 + (n - 256)];
    } else              a = Wout[k * 256 + (ng - 640)];
    wt[idx] = __float2half_rn(a);
    if (idx < 384) bqc[idx] = (idx < 256) ? boff[idx] : battn[idx - 256];
}

// ---------------- GEMM v1 (R11): fp32 A fused-convert, BM=128 BN=128 --------
constexpr int ASTG  = 10240;                       // A buffer (fp16)
constexpr int BSTG  = 10240;                       // B stage (fp16)
constexpr int BBASE = 2 * ASTG;                    // 20480
constexpr int GSMEM = BBASE + 3 * BSTG;            // 51200 -> 2 CTAs/SM

template <bool HalfOut>
__device__ __forceinline__ void gemm_core(
    const float* __restrict__ A,
    const __half* __restrict__ B,
    const float* __restrict__ bias, void* __restrict__ Cv,
    int M, int ldc, int m0, int n0, char* smem)
{
    const uint32_t sm0 = smem_u32(smem);
    const int tid = threadIdx.x, wid = tid >> 5, lane = tid & 31;
    const int wm = (wid & 3) * 32, wn = (wid >> 2) * 64;

    const int arow = tid >> 1, ak0 = (tid & 1) * 16;
    const bool avalid = (m0 + arow) < M;
    const float* aptr = A + (size_t)(m0 + arow) * 256 + ak0;

    const int brow = tid >> 1, bc2 = (tid & 1) * 2;

    const uint32_t aRow = (lane & 15), aColB = (uint32_t)(lane >> 4) * 16;
    const uint32_t bRow = ((uint32_t)(lane >> 4) << 3) + (lane & 7);
    const uint32_t bColB = (uint32_t)((lane >> 3) & 1) * 16;

    float acc[2][8][4] = {};
    float fA[16];

    auto ldgA = [&](int ch) {
        if (avalid) {
            const float* p = aptr + ch * 32;
            #pragma unroll
            for (int j = 0; j < 4; ++j)
                *(float4*)&fA[j * 4] = *(const float4*)(p + j * 4);
        } else {
            #pragma unroll
            for (int j = 0; j < 16; ++j) fA[j] = 0.f;
        }
    };
    auto cvtStoreA = [&](uint32_t off) {
        __half h[16];
        #pragma unroll
        for (int j = 0; j < 16; ++j) h[j] = __float2half_rn(fA[j]);
        const uint32_t o = arow * 80 + ak0 * 2;
        *(uint4*)(smem + off + o)      = ((uint4*)h)[0];
        *(uint4*)(smem + off + o + 16) = ((uint4*)h)[1];
    };
    auto ldB = [&](int ch) {
        const uint32_t sb = sm0 + BBASE + (ch % 3) * BSTG;
        const int k0 = ch * 32;
        #pragma unroll
        for (int i = 0; i < 2; ++i) {
            const int c = bc2 + i;
            CP_ASYNC16(sb + brow * 80 + c * 16,
                       B + (size_t)(n0 + brow) * 256 + k0 + c * 8);
        }
        CP_COMMIT();
    };

    ldB(0); ldB(1);
    ldgA(0);
    cvtStoreA(0);

    for (int ch = 0; ch < 8; ++ch) {
        CP_WAIT1();
        __syncthreads();
        if (ch < 6) ldB(ch + 2); else CP_COMMIT();
        if (ch < 7) ldgA(ch + 1);

        const uint32_t sa = sm0 + (ch & 1) * ASTG;
        const uint32_t sb = sm0 + BBASE + (ch % 3) * BSTG;
        #pragma unroll
        for (int ks = 0; ks < 2; ++ks) {
            const uint32_t kB = ks * 32;
            uint32_t af[2][4], bf[4][4];
            #pragma unroll
            for (int mt = 0; mt < 2; ++mt)
                ldsm_x4(sa + (wm + mt * 16 + aRow) * 80 + kB + aColB, af[mt]);
            #pragma unroll
            for (int p = 0; p < 4; ++p)
                ldsm_x4(sb + (wn + p * 16 + bRow) * 80 + kB + bColB, bf[p]);
            #pragma unroll
            for (int mt = 0; mt < 2; ++mt)
                #pragma unroll
                for (int nt = 0; nt < 8; ++nt)
                    mma_f16(acc[mt][nt], af[mt], &bf[nt >> 1][(nt & 1) * 2]);
        }

        if (ch < 7) cvtStoreA(((ch + 1) & 1) * ASTG);
    }

    const int g = lane >> 2, t2 = (lane & 3) * 2;
    #pragma unroll
    for (int mt = 0; mt < 2; ++mt) {
        const int r0 = m0 + wm + mt * 16 + g;
        #pragma unroll
        for (int nt = 0; nt < 8; ++nt) {
            const int c = n0 + wn + nt * 8 + t2;
            const float2 bsv = *(const float2*)(bias + c);
            if (HalfOut) {
                __half* C = (__half*)Cv;
                if (r0 < M)
                    *(__half2*)(C + (size_t)r0 * ldc + c) =
                        __floats2half2_rn(acc[mt][nt][0] + bsv.x, acc[mt][nt][1] + bsv.y);
                if (r0 + 8 < M)
                    *(__half2*)(C + (size_t)(r0 + 8) * ldc + c) =
                        __floats2half2_rn(acc[mt][nt][2] + bsv.x, acc[mt][nt][3] + bsv.y);
            } else {
                float* C = (float*)Cv;
                if (r0 < M) {
                    float2 o = { acc[mt][nt][0] + bsv.x, acc[mt][nt][1] + bsv.y };
                    *(float2*)(C + (size_t)r0 * ldc + c) = o;
                }
                if (r0 + 8 < M) {
                    float2 o = { acc[mt][nt][2] + bsv.x, acc[mt][nt][3] + bsv.y };
                    *(float2*)(C + (size_t)(r0 + 8) * ldc + c) = o;
                }
            }
        }
    }
}

// merged value+qc GEMM: grid.y in [0,5): y<2 -> value fp16 (N=256), y>=2 -> qc fp32 (N=384)
__global__ __launch_bounds__(256, 2) void gemm_dual(
    const float* __restrict__ A0, const __half* __restrict__ B0,
    const float* __restrict__ bias0, __half* __restrict__ C0,
    const float* __restrict__ A1, const __half* __restrict__ B1,
    const float* __restrict__ bias1, float* __restrict__ C1)
{
    extern __shared__ __align__(16) char smem[];
    const int m0 = blockIdx.x * 128;
    if (blockIdx.y < 2)
        gemm_core<true >(A0, B0, bias0, C0, MROWS, 256, m0, blockIdx.y * 128, smem);
    else
        gemm_core<false>(A1, B1, bias1, C1, MROWS, 384, m0, (blockIdx.y - 2) * 128, smem);
}

// ---------------- GEMM v2: fp16 A via cp.async (output GEMM) ----------------
// Both A and B: 3-stage cp.async rings, one commit group per chunk.
constexpr int ASTG2  = 10240;
constexpr int BSTG2  = 10240;
constexpr int BBASE2 = 3 * ASTG2;                  // 30720
constexpr int GSMEM2 = BBASE2 + 3 * BSTG2;         // 61440 -> 2 CTAs/SM

__global__ __launch_bounds__(256, 2) void gemm_single_h(
    const __half* __restrict__ A, const __half* __restrict__ B,
    const float* __restrict__ bias, float* __restrict__ C, int M, int ldc)
{
    extern __shared__ __align__(16) char smem[];
    const uint32_t sm0 = smem_u32(smem);
    const int tid = threadIdx.x, wid = tid >> 5, lane = tid & 31;
    const int m0 = blockIdx.x * 128, n0 = blockIdx.y * 128;
    const int wm = (wid & 3) * 32, wn = (wid >> 2) * 64;

    const int row = tid >> 1, c2 = (tid & 1) * 2;

    const uint32_t aRow = (lane & 15), aColB = (uint32_t)(lane >> 4) * 16;
    const uint32_t bRow = ((uint32_t)(lane >> 4) << 3) + (lane & 7);
    const uint32_t bColB = (uint32_t)((lane >> 3) & 1) * 16;

    float acc[2][8][4] = {};

    auto ldAB = [&](int ch) {
        const uint32_t sa = sm0 + (ch % 3) * ASTG2;
        const uint32_t sb = sm0 + BBASE2 + (ch % 3) * BSTG2;
        const int k0 = ch * 32;
        #pragma unroll
        for (int i = 0; i < 2; ++i) {
            const int c = c2 + i;
            CP_ASYNC16(sa + row * 80 + c * 16, A + (size_t)(m0 + row) * 256 + k0 + c * 8);
            CP_ASYNC16(sb + row * 80 + c * 16, B + (size_t)(n0 + row) * 256 + k0 + c * 8);
        }
        CP_COMMIT();
    };

    ldAB(0); ldAB(1);

    for (int ch = 0; ch < 8; ++ch) {
        CP_WAIT1();
        __syncthreads();
        if (ch < 6) ldAB(ch + 2); else CP_COMMIT();

        const uint32_t sa = sm0 + (ch % 3) * ASTG2;
        const uint32_t sb = sm0 + BBASE2 + (ch % 3) * BSTG2;
        #pragma unroll
        for (int ks = 0; ks < 2; ++ks) {
            const uint32_t kB = ks * 32;
            uint32_t af[2][4], bf[4][4];
            #pragma unroll
            for (int mt = 0; mt < 2; ++mt)
                ldsm_x4(sa + (wm + mt * 16 + aRow) * 80 + kB + aColB, af[mt]);
            #pragma unroll
            for (int p = 0; p < 4; ++p)
                ldsm_x4(sb + (wn + p * 16 + bRow) * 80 + kB + bColB, bf[p]);
            #pragma unroll
            for (int mt = 0; mt < 2; ++mt)
                #pragma unroll
                for (int nt = 0; nt < 8; ++nt)
                    mma_f16(acc[mt][nt], af[mt], &bf[nt >> 1][(nt & 1) * 2]);
        }
    }

    const int g = lane >> 2, t2 = (lane & 3) * 2;
    #pragma unroll
    for (int mt = 0; mt < 2; ++mt) {
        const int r0 = m0 + wm + mt * 16 + g;
        #pragma unroll
        for (int nt = 0; nt < 8; ++nt) {
            const int c = n0 + wn + nt * 8 + t2;
            const float2 bsv = *(const float2*)(bias + c);
            if (r0 < M) {
                float2 o = { acc[mt][nt][0] + bsv.x, acc[mt][nt][1] + bsv.y };
                *(float2*)(C + (size_t)r0 * ldc + c) = o;
            }
            if (r0 + 8 < M) {
                float2 o = { acc[mt][nt][2] + bsv.x, acc[mt][nt][3] + bsv.y };
                *(float2*)(C + (size_t)(r0 + 8) * ldc + c) = o;
            }
        }
    }
}

// ---------------- deformable sampling: fp16 in, fp16 out ----------------
__global__ __launch_bounds__(256) void sample_kernel(
    const float* __restrict__ refpts,   // [N*Lq, 4, 2]
    const __half* __restrict__ value,   // [N*S, 256] fp16
    const float* __restrict__ qc,       // [N*Lq, 384]: off(256) | logits(128)
    __half* __restrict__ out)           // [N*Lq, 256] fp16
{
    const int q0  = blockIdx.x * 4;
    const int tid = threadIdx.x;

    __shared__ float sh_w[4][8][17];
    __shared__ float sh_x[4][8][17];
    __shared__ float sh_y[4][8][17];
    __shared__ __align__(16) float2 sh_p[4][8][64];

    // softmax weights: 32 runs of 16 logits, 16-lane segments
    #pragma unroll
    for (int i = 0; i < 2; ++i) {
        int run = i * 16 + (tid >> 4);
        int q = run >> 3, h = run & 7, l16 = tid & 15;
        float v = qc[(size_t)(q0 + q) * 384 + 256 + h * 16 + l16];
        float mx = v;
        #pragma unroll
        for (int o = 8; o > 0; o >>= 1) mx = fmaxf(mx, __shfl_xor_sync(0xffffffffu, mx, o));
        float e = __expf(v - mx);
        float s = e;
        #pragma unroll
        for (int o = 8; o > 0; o >>= 1) s += __shfl_xor_sync(0xffffffffu, s, o);
        sh_w[q][h][l16] = e / s;
    }

    // pixel coords: x = ref*W + off - 0.5
    #pragma unroll
    for (int q = 0; q < 4; ++q) {
        int h = tid >> 5, l32 = tid & 31;
        int lvl = l32 >> 3, cc = l32 & 1, s = l32 >> 1;
        float off = qc[(size_t)(q0 + q) * 384 + tid];
        float ref = refpts[((size_t)(q0 + q) * 4 + lvl) * 2 + cc];
        float pix = fmaf(ref, (float)c_WH[lvl], off) - 0.5f;
        if (cc == 0) sh_x[q][h][s] = pix; else sh_y[q][h][s] = pix;
    }
    __syncthreads();

    // 2048 corners, 8 per thread: (q,h,s,c) -> (gw, byteoff)  [512B per position]
    #pragma unroll
    for (int i = 0; i < 8; ++i) {
        const int e = i * 256 + tid;
        const int q = e >> 9, h = (e >> 6) & 7, s = (e >> 2) & 15, c = e & 3;
        const int lvl = s >> 2;
        const int Wl = c_WH[lvl], st = c_ST[lvl];
        const float x = sh_x[q][h][s], y = sh_y[q][h][s], aw = sh_w[q][h][s];
        const float xf = floorf(x), yf = floorf(y);
        const float wx = x - xf, wy = y - yf;
        const int xi = (int)xf + (c & 1);
        const int yi = (int)yf + (c >> 1);
        const float gw = aw * ((c >> 1) ? wy : 1.f - wy) * ((c & 1) ? wx : 1.f - wx);
        const bool valid = (xi >= 0) & (xi < Wl) & (yi >= 0) & (yi < Wl);
        float2 pr;
        pr.x = valid ? gw : 0.f;
        pr.y = __int_as_float(valid ? (st + yi * Wl + xi) * 512 : 0);
        sh_p[q][h][s * 4 + c] = pr;
    }
    __syncthreads();

    // gather: warp = (query, head-half); lane: 4 heads x 8 slots of 4 fp16 channels
    const int w = tid >> 5, lane = tid & 31;
    const int q = w >> 1, half = w & 1;
    const int head = half * 4 + (lane >> 3);
    const int ci = lane & 7;
    const int qg = q0 + q;
    const int n  = (qg >= LQ) ? 1 : 0;

    const char* vb = (const char*)value + ((size_t)n * LQ * 256 + head * 32 + ci * 4) * 2;
    const float4* pp = (const float4*)&sh_p[q][head][0];
    float4 acc = make_float4(0.f, 0.f, 0.f, 0.f);

    #pragma unroll 8
    for (int i = 0; i < 32; ++i) {
        const float4 pw = pp[i];
        const uint2 r0 = __ldg((const uint2*)(vb + (uint32_t)__float_as_int(pw.y)));
        const uint2 r1 = __ldg((const uint2*)(vb + (uint32_t)__float_as_int(pw.w)));
        const float2 a0 = __half22float2(*(const __half2*)&r0.x);
        const float2 a1 = __half22float2(*(const __half2*)&r0.y);
        const float2 b0 = __half22float2(*(const __half2*)&r1.x);
        const float2 b1 = __half22float2(*(const __half2*)&r1.y);
        acc.x = fmaf(pw.x, a0.x, acc.x);
        acc.y = fmaf(pw.x, a0.y, acc.y);
        acc.z = fmaf(pw.x, a1.x, acc.z);
        acc.w = fmaf(pw.x, a1.y, acc.w);
        acc.x = fmaf(pw.z, b0.x, acc.x);
        acc.y = fmaf(pw.z, b0.y, acc.y);
        acc.z = fmaf(pw.z, b1.x, acc.z);
        acc.w = fmaf(pw.z, b1.y, acc.w);
    }

    __half2 o01 = __floats2half2_rn(acc.x, acc.y);
    __half2 o23 = __floats2half2_rn(acc.z, acc.w);
    uint2 ov = { *(uint32_t*)&o01, *(uint32_t*)&o23 };
    *(uint2*)(out + (size_t)qg * 256 + head * 32 + ci * 4) = ov;
}

// ---------------- launch (single stream) ----------------
extern "C" void kernel_launch(void* const* d_in, const int* in_sizes, int n_in,
                              void* d_out, int out_size)
{
    const float* query  = (const float*)d_in[0];
    const float* refpts = (const float*)d_in[1];
    const float* flat   = (const float*)d_in[2];
    const float* Wv     = (const float*)d_in[5];
    const float* bv     = (const float*)d_in[6];
    const float* Woff   = (const float*)d_in[7];
    const float* boff   = (const float*)d_in[8];
    const float* Wattn  = (const float*)d_in[9];
    const float* battn  = (const float*)d_in[10];
    const float* Wout   = (const float*)d_in[11];
    const float* bout   = (const float*)d_in[12];
    float* out = (float*)d_out;

    __half *gv, *gs, *wt;
    float *gqc, *gbqc;
    cudaGetSymbolAddress((void**)&gv,   g_value);
    cudaGetSymbolAddress((void**)&gqc,  g_qc);
    cudaGetSymbolAddress((void**)&gs,   g_samp);
    cudaGetSymbolAddress((void**)&gbqc, g_bqc);
    cudaGetSymbolAddress((void**)&wt,   g_wt);

    static bool attr_done = false;
    if (!attr_done) {
        cudaFuncSetAttribute(gemm_dual,     cudaFuncAttributeMaxDynamicSharedMemorySize, GSMEM);
        cudaFuncSetAttribute(gemm_single_h, cudaFuncAttributeMaxDynamicSharedMemorySize, GSMEM2);
        attr_done = true;
    }

    __half *wv = wt + 0, *wq = wt + 256 * 256, *wu = wt + 640 * 256;

    conv_wt_all<<<896, 256>>>(Wv, Woff, Wattn, Wout, boff, battn, wt, gbqc);

    const int mblk = MPAD / 128;           // 208
    gemm_dual<<<dim3(mblk, 5), 256, GSMEM>>>(flat, wv, bv, gv,
                                             query, wq, gbqc, gqc);
    sample_kernel<<<MROWS / 4, 256>>>(refpts, gv, gqc, gs);
    gemm_single_h<<<dim3(mblk, 2), 256, GSMEM2>>>(gs, wu, bout, out, MROWS, 256);
}